// round 1
// baseline (speedup 1.0000x reference)
#include <cuda_runtime.h>

// ---------------- scratch (static device globals; no allocation) ----------------
__device__ float g_wav[64 * 768 * 196];          // 38.5 MB  [b][ch][14*14]
__device__ float g_sp1[64 * 192 * 56 * 56];      // 154 MB   [b][oc][56][56]
__device__ float g_sp2[64 * 192 * 196];          // 9.6 MB   [b][oc][14*14]

// ---------------- 4-level Haar == 16x16 2D Walsh-Hadamard per tile ----------------
// out[b, k*3+c, i, j] with k = sum_l k_l * 4^(4-l), k_l = 2*rowbit(l-1) + colbit(l-1)
__global__ void haar_kernel(const float* __restrict__ x) {
    int bid  = blockIdx.x;
    int tile = bid % 196;          // i*14 + j
    int bc   = bid / 196;          // b*3 + c
    int c    = bc % 3;
    int b    = bc / 3;
    int ti = tile / 14, tj = tile % 14;
    int t  = threadIdx.x;          // 0..255
    int dy = t >> 4, dx = t & 15;

    __shared__ float s[256];
    float v = x[((b * 3 + c) * 224 + ti * 16 + dy) * 224 + tj * 16 + dx];

#pragma unroll
    for (int st = 0; st < 8; ++st) {
        s[t] = v;
        __syncthreads();
        float u = s[t ^ (1 << st)];
        v = (t & (1 << st)) ? (u - v) : (v + u);
        __syncthreads();
    }

    // thread t now holds WHT coefficient (rm = t>>4 over dy-bits, cm = t&15 over dx-bits)
    int cm = t & 15, rm = t >> 4;
    int k1 = 2 * ((rm >> 0) & 1) + ((cm >> 0) & 1);
    int k2 = 2 * ((rm >> 1) & 1) + ((cm >> 1) & 1);
    int k3 = 2 * ((rm >> 2) & 1) + ((cm >> 2) & 1);
    int k4 = 2 * ((rm >> 3) & 1) + ((cm >> 3) & 1);
    int k  = ((k1 * 4 + k2) * 4 + k3) * 4 + k4;
    int ch = k * 3 + c;
    g_wav[(b * 768 + ch) * 196 + tile] = v * 0.0625f;   // (0.5)^4
}

// ---------------- implicit-GEMM conv with fused im2col gather ----------------
// MODE 1: conv1  x[64,3,224,224] * w[192,3,7,7]  s4 p3 -> g_sp1 [64,192,56,56]
//         M=192  N=64*3136=200704  K=147
// MODE 2: conv2  g_sp1 * w[192,192,7,7] s4 p3 -> g_sp2 [64,192,14,14]
//         M=192  N=64*196=12544     K=9408
// MODE 3: conv_p feat(wav||sp2)[960ch,14,14] * w[768,960,3,3] s2 p1
//         -> d_out[b][1+p][oc] (+bias +positions)   M=768 N=64*49=3136 K=8640
template <int MODE>
__global__ void __launch_bounds__(256)
conv_gemm(const float* __restrict__ A,      // weights [M][K]
          const float* __restrict__ bias,   // [M]
          const float* __restrict__ X,      // MODE 1 input (x); unused otherwise
          const float* __restrict__ positions, // MODE 3
          float* __restrict__ Cout)            // MODE 3 (d_out)
{
    constexpr int K = (MODE == 1) ? 147 : (MODE == 2) ? 9408 : 8640;

    const int m0  = blockIdx.y * 64;
    const int n0  = blockIdx.x * 64;
    const int tid = threadIdx.x;

    __shared__ float As[16][64];
    __shared__ float Bs[16][64];

    // A-load mapping: thread -> (row m, 4 consecutive k)
    const int am = tid >> 2;           // 0..63
    const int ak = (tid & 3) * 4;      // 0,4,8,12
    // B-load mapping: thread -> (col n, k rows bk, bk+4, bk+8, bk+12)
    const int bn = tid & 63;
    const int bk = tid >> 6;           // 0..3

    // decompose this thread's gather column once
    const int ng = n0 + bn;
    int b_, oy_, ox_;
    if (MODE == 1)      { b_ = ng / 3136; int p = ng % 3136; oy_ = p / 56; ox_ = p % 56; }
    else if (MODE == 2) { b_ = ng / 196;  int p = ng % 196;  oy_ = p / 14; ox_ = p % 14; }
    else                { b_ = ng / 49;   int p = ng % 49;   oy_ = p / 7;  ox_ = p % 7;  }

    const int tm = (tid >> 4) * 4;
    const int tn = (tid & 15) * 4;

    float acc[4][4] = {};
    const float* Arow = A + (m0 + am) * K;

    for (int k0 = 0; k0 < K; k0 += 16) {
        // stage A
#pragma unroll
        for (int i = 0; i < 4; ++i) {
            int k = k0 + ak + i;
            As[ak + i][am] = (k < K) ? Arow[k] : 0.f;
        }
        // stage B (fused im2col gather)
#pragma unroll
        for (int i = 0; i < 4; ++i) {
            int kk = bk + i * 4;
            int k  = k0 + kk;
            float val = 0.f;
            if (k < K) {
                if (MODE == 1) {
                    int c = k / 49, r = k % 49, ky = r / 7, kx = r % 7;
                    int iy = oy_ * 4 + ky - 3, ix = ox_ * 4 + kx - 3;
                    if (iy >= 0 && iy < 224 && ix >= 0 && ix < 224)
                        val = X[((b_ * 3 + c) * 224 + iy) * 224 + ix];
                } else if (MODE == 2) {
                    int c = k / 49, r = k % 49, ky = r / 7, kx = r % 7;
                    int iy = oy_ * 4 + ky - 3, ix = ox_ * 4 + kx - 3;
                    if (iy >= 0 && iy < 56 && ix >= 0 && ix < 56)
                        val = g_sp1[((b_ * 192 + c) * 56 + iy) * 56 + ix];
                } else {
                    int ch = k / 9, r = k % 9, ky = r / 3, kx = r % 3;
                    int iy = oy_ * 2 + ky - 1, ix = ox_ * 2 + kx - 1;
                    if (iy >= 0 && iy < 14 && ix >= 0 && ix < 14) {
                        val = (ch < 768)
                                  ? g_wav[(b_ * 768 + ch) * 196 + iy * 14 + ix]
                                  : g_sp2[(b_ * 192 + (ch - 768)) * 196 + iy * 14 + ix];
                    }
                }
            }
            Bs[kk][bn] = val;
        }
        __syncthreads();

#pragma unroll
        for (int kk = 0; kk < 16; ++kk) {
            float a[4], bb[4];
#pragma unroll
            for (int i = 0; i < 4; ++i) a[i] = As[kk][tm + i];
#pragma unroll
            for (int j = 0; j < 4; ++j) bb[j] = Bs[kk][tn + j];
#pragma unroll
            for (int i = 0; i < 4; ++i)
#pragma unroll
                for (int j = 0; j < 4; ++j) acc[i][j] += a[i] * bb[j];
        }
        __syncthreads();
    }

    // epilogue
#pragma unroll
    for (int i = 0; i < 4; ++i) {
        int oc = m0 + tm + i;
        float bi = bias[oc];
#pragma unroll
        for (int j = 0; j < 4; ++j) {
            int nn = n0 + tn + j;
            float v = acc[i][j] + bi;
            if (MODE == 1) {
                int b = nn / 3136, p = nn % 3136;
                g_sp1[(b * 192 + oc) * 3136 + p] = v;
            } else if (MODE == 2) {
                int b = nn / 196, p = nn % 196;
                g_sp2[(b * 192 + oc) * 196 + p] = v;
            } else {
                int b = nn / 49, p = nn % 49;
                Cout[(b * 50 + 1 + p) * 768 + oc] = v + positions[(1 + p) * 768 + oc];
            }
        }
    }
}

// ---------------- cls row: out[b][0][:] = cls + positions[0] ----------------
__global__ void cls_kernel(const float* __restrict__ cls,
                           const float* __restrict__ pos,
                           float* __restrict__ out) {
    int i = blockIdx.x * 256 + threadIdx.x;   // 64*768
    if (i < 64 * 768) {
        int b = i / 768, oc = i % 768;
        out[(b * 50) * 768 + oc] = cls[oc] + pos[oc];
    }
}

extern "C" void kernel_launch(void* const* d_in, const int* in_sizes, int n_in,
                              void* d_out, int out_size) {
    const float* x   = (const float*)d_in[0];
    const float* w1  = (const float*)d_in[1];
    const float* b1  = (const float*)d_in[2];
    const float* w2  = (const float*)d_in[3];
    const float* b2  = (const float*)d_in[4];
    const float* wp  = (const float*)d_in[5];
    const float* bp  = (const float*)d_in[6];
    const float* cls = (const float*)d_in[7];
    const float* pos = (const float*)d_in[8];
    float* out = (float*)d_out;

    // Haar wavelet pyramid -> g_wav
    haar_kernel<<<64 * 3 * 196, 256>>>(x);

    // conv1: x -> g_sp1
    conv_gemm<1><<<dim3(200704 / 64, 192 / 64), 256>>>(w1, b1, x, nullptr, nullptr);

    // conv2: g_sp1 -> g_sp2
    conv_gemm<2><<<dim3(12544 / 64, 192 / 64), 256>>>(w2, b2, nullptr, nullptr, nullptr);

    // conv_p: (g_wav || g_sp2) -> d_out (bias + positions + transpose fused)
    conv_gemm<3><<<dim3(3136 / 64, 768 / 64), 256>>>(wp, bp, nullptr, pos, out);

    // cls row
    cls_kernel<<<192, 256>>>(cls, pos, out);
}

// round 2
// speedup vs baseline: 1.1115x; 1.1115x over previous
#include <cuda_runtime.h>

// ---------------- scratch (static device globals; no allocation) ----------------
__device__ float g_wav[64 * 768 * 196];     // 38.5 MB  [b][ch][14*14]
__device__ float g_sp2[64 * 192 * 196];     // 9.6 MB   [b][oc][14*14]
__device__ float g_wcomp[192 * 3 * 31 * 31];// composed conv1∘conv2 weights [o][c][31][31]
__device__ float g_bias[192 * 4];           // composed bias, 4 border cases per oc

// ---------------- 4-level Haar == 16x16 2D Walsh-Hadamard per tile ----------------
__global__ void haar_kernel(const float* __restrict__ x) {
    int bid  = blockIdx.x;
    int tile = bid % 196;
    int bc   = bid / 196;
    int c    = bc % 3;
    int b    = bc / 3;
    int ti = tile / 14, tj = tile % 14;
    int t  = threadIdx.x;
    int dy = t >> 4, dx = t & 15;

    __shared__ float s[256];
    float v = x[((b * 3 + c) * 224 + ti * 16 + dy) * 224 + tj * 16 + dx];

#pragma unroll
    for (int st = 0; st < 8; ++st) {
        s[t] = v;
        __syncthreads();
        float u = s[t ^ (1 << st)];
        v = (t & (1 << st)) ? (u - v) : (v + u);
        __syncthreads();
    }

    int cm = t & 15, rm = t >> 4;
    int k1 = 2 * ((rm >> 0) & 1) + ((cm >> 0) & 1);
    int k2 = 2 * ((rm >> 1) & 1) + ((cm >> 1) & 1);
    int k3 = 2 * ((rm >> 2) & 1) + ((cm >> 2) & 1);
    int k4 = 2 * ((rm >> 3) & 1) + ((cm >> 3) & 1);
    int k  = ((k1 * 4 + k2) * 4 + k3) * 4 + k4;
    int ch = k * 3 + c;
    g_wav[(b * 768 + ch) * 196 + tile] = v * 0.0625f;
}

// ---------------- compose w_comp[o][c][dy][dx] = sum_m w2[o][m] ⊛ w1[m][c] -------
// tap d = 4*k2 + k1 (d in [0,30] per axis), stride 16, pad 15 composite conv.
__global__ void compose_kernel(const float* __restrict__ w1,
                               const float* __restrict__ w2) {
    int o = blockIdx.x;                    // 0..191
    __shared__ float s_w2[192 * 49];
    for (int i = threadIdx.x; i < 192 * 49; i += blockDim.x)
        s_w2[i] = w2[o * 192 * 49 + i];
    __syncthreads();

    for (int r = threadIdx.x; r < 2883; r += blockDim.x) {
        int c  = r / 961;
        int r2 = r - c * 961;
        int dy = r2 / 31, dx = r2 - (r2 / 31) * 31;
        float acc = 0.f;
#pragma unroll
        for (int ky2 = 0; ky2 < 7; ++ky2) {
            int ky1 = dy - 4 * ky2;
            if (ky1 < 0 || ky1 > 6) continue;
#pragma unroll
            for (int kx2 = 0; kx2 < 7; ++kx2) {
                int kx1 = dx - 4 * kx2;
                if (kx1 < 0 || kx1 > 6) continue;
                const float* w2p = &s_w2[(ky2) * 7 + kx2];
                const float* w1p = &w1[(c * 7 + ky1) * 7 + kx1];
                for (int m = 0; m < 192; ++m)
                    acc += w2p[m * 49] * w1p[m * 147];
            }
        }
        g_wcomp[o * 2883 + r] = acc;
    }
}

// ---------------- composed bias: 4 border cases per output channel --------------
// case idx = (oy==0)*2 + (ox==0): taps ky2<3 dropped when oy==0, kx2<3 when ox==0
__global__ void bias_kernel(const float* __restrict__ w2,
                            const float* __restrict__ b1,
                            const float* __restrict__ b2) {
    int o = blockIdx.x;
    int m = threadIdx.x;                    // blockDim = 256, active m < 192
    float s00 = 0, s01 = 0, s10 = 0, s11 = 0;
    if (m < 192) {
        float bm = b1[m];
#pragma unroll
        for (int ky2 = 0; ky2 < 7; ++ky2)
#pragma unroll
            for (int kx2 = 0; kx2 < 7; ++kx2) {
                float w = w2[((o * 192 + m) * 7 + ky2) * 7 + kx2] * bm;
                s00 += w;
                if (kx2 >= 3) s01 += w;
                if (ky2 >= 3) s10 += w;
                if (ky2 >= 3 && kx2 >= 3) s11 += w;
            }
    }
    __shared__ float red[4][256];
    red[0][m] = s00; red[1][m] = s01; red[2][m] = s10; red[3][m] = s11;
    __syncthreads();
    for (int s = 128; s > 0; s >>= 1) {
        if (m < s) {
            red[0][m] += red[0][m + s];
            red[1][m] += red[1][m + s];
            red[2][m] += red[2][m + s];
            red[3][m] += red[3][m + s];
        }
        __syncthreads();
    }
    if (m == 0) {
        float bo = b2[o];
        g_bias[o * 4 + 0] = bo + red[0][0];
        g_bias[o * 4 + 1] = bo + red[1][0];
        g_bias[o * 4 + 2] = bo + red[2][0];
        g_bias[o * 4 + 3] = bo + red[3][0];
    }
}

// ---------------- implicit-GEMM convs ----------------
// MODE 2: composite conv  x[64,3,224,224] * g_wcomp[192,3,31,31] s16 p15 -> g_sp2
//         M=192 N=12544 K=2883, BM=64 BN=128, 4x8 micro
// MODE 3: conv_p (g_wav||g_sp2)[960ch,14,14] * w[768,960,3,3] s2 p1 -> d_out
//         M=768 N=3136 K=8640, BM=128 BN=128, 8x8 micro
template <int MODE>
__global__ void __launch_bounds__(256)
conv_gemm(const float* __restrict__ A,
          const float* __restrict__ bias,
          const float* __restrict__ X,
          const float* __restrict__ positions,
          float* __restrict__ Cout)
{
    constexpr int BM = (MODE == 2) ? 64 : 128;
    constexpr int BN = 128;
    constexpr int TM = (MODE == 2) ? 4 : 8;
    constexpr int TN = 8;
    constexpr int K  = (MODE == 2) ? 2883 : 8640;
    constexpr int NT = (MODE == 2) ? 12544 : 3136;
    constexpr int AKPT = 16 * BM / 256;          // consecutive-k per thread (4 or 8)
    constexpr int AGRP = 16 / AKPT;              // threads per A-row

    __shared__ float As[16][BM + 4];
    __shared__ float Bs[16][BN + 4];

    const int tid = threadIdx.x;
    const int m0 = blockIdx.y * BM;
    const int n0 = blockIdx.x * BN;

    const float* Aptr = (MODE == 2) ? (const float*)g_wcomp : A;

    const int am = tid / AGRP;
    const int ak = (tid % AGRP) * AKPT;
    const float* Abase = Aptr + (m0 + am) * K;

    const int bn  = tid & 127;
    const int bkb = (tid >> 7) * 8;

    const int ng = n0 + bn;
    const bool bvalid = (ng < NT);
    int b_, oy_, ox_;
    {
        int nn = bvalid ? ng : 0;
        if (MODE == 2) { b_ = nn / 196; int p = nn % 196; oy_ = p / 14; ox_ = p % 14; }
        else           { b_ = nn / 49;  int p = nn % 49;  oy_ = p / 7;  ox_ = p % 7;  }
    }

    const int ty = tid >> 4, tx = tid & 15;
    const int tm = ty * TM, tn = tx * TN;

    float acc[TM][TN] = {};

    for (int k0 = 0; k0 < K; k0 += 16) {
        // stage A
#pragma unroll
        for (int i = 0; i < AKPT; ++i) {
            int k = k0 + ak + i;
            float v;
            if (K % 16 == 0) v = Abase[k];
            else             v = (k < K) ? Abase[k] : 0.f;
            As[ak + i][am] = v;
        }
        // stage B (fused im2col gather)
#pragma unroll
        for (int i = 0; i < 8; ++i) {
            int kk = bkb + i;
            int k  = k0 + kk;
            float val = 0.f;
            if ((K % 16 == 0 || k < K) && bvalid) {
                if (MODE == 2) {
                    int c = k / 961; int r = k - c * 961;
                    int dy = r / 31; int dx = r - dy * 31;
                    int iy = oy_ * 16 + dy - 15, ix = ox_ * 16 + dx - 15;
                    if ((unsigned)iy < 224u && (unsigned)ix < 224u)
                        val = X[((b_ * 3 + c) * 224 + iy) * 224 + ix];
                } else {
                    int ch = k / 9; int r = k - ch * 9;
                    int ky = r / 3; int kx = r - ky * 3;
                    int iy = oy_ * 2 + ky - 1, ix = ox_ * 2 + kx - 1;
                    if ((unsigned)iy < 14u && (unsigned)ix < 14u) {
                        val = (ch < 768)
                                  ? g_wav[(b_ * 768 + ch) * 196 + iy * 14 + ix]
                                  : g_sp2[(b_ * 192 + (ch - 768)) * 196 + iy * 14 + ix];
                    }
                }
            }
            Bs[kk][bn] = val;
        }
        __syncthreads();

#pragma unroll
        for (int kk = 0; kk < 16; ++kk) {
            float a[TM], bb[TN];
#pragma unroll
            for (int i = 0; i < TM; ++i) a[i] = As[kk][tm + i];
#pragma unroll
            for (int j = 0; j < TN; ++j) bb[j] = Bs[kk][tn + j];
#pragma unroll
            for (int i = 0; i < TM; ++i)
#pragma unroll
                for (int j = 0; j < TN; ++j) acc[i][j] += a[i] * bb[j];
        }
        __syncthreads();
    }

    // epilogue
#pragma unroll
    for (int i = 0; i < TM; ++i) {
        int oc = m0 + tm + i;
#pragma unroll
        for (int j = 0; j < TN; ++j) {
            int nn = n0 + tn + j;
            if (MODE == 2) {
                int b = nn / 196, p = nn % 196;
                int oy = p / 14, ox = p % 14;
                float bi = g_bias[oc * 4 + (oy == 0 ? 2 : 0) + (ox == 0 ? 1 : 0)];
                g_sp2[(b * 192 + oc) * 196 + p] = acc[i][j] + bi;
            } else {
                if (nn < NT) {
                    int b = nn / 49, p = nn % 49;
                    Cout[(b * 50 + 1 + p) * 768 + oc] =
                        acc[i][j] + bias[oc] + positions[(1 + p) * 768 + oc];
                }
            }
        }
    }
}

// ---------------- cls row ----------------
__global__ void cls_kernel(const float* __restrict__ cls,
                           const float* __restrict__ pos,
                           float* __restrict__ out) {
    int i = blockIdx.x * 256 + threadIdx.x;
    if (i < 64 * 768) {
        int b = i / 768, oc = i % 768;
        out[(b * 50) * 768 + oc] = cls[oc] + pos[oc];
    }
}

extern "C" void kernel_launch(void* const* d_in, const int* in_sizes, int n_in,
                              void* d_out, int out_size) {
    const float* x   = (const float*)d_in[0];
    const float* w1  = (const float*)d_in[1];
    const float* b1  = (const float*)d_in[2];
    const float* w2  = (const float*)d_in[3];
    const float* b2  = (const float*)d_in[4];
    const float* wp  = (const float*)d_in[5];
    const float* bp  = (const float*)d_in[6];
    const float* cls = (const float*)d_in[7];
    const float* pos = (const float*)d_in[8];
    float* out = (float*)d_out;

    // Haar wavelet pyramid -> g_wav
    haar_kernel<<<64 * 3 * 196, 256>>>(x);

    // compose conv1*conv2 weights + border bias
    compose_kernel<<<192, 256>>>(w1, w2);
    bias_kernel<<<192, 256>>>(w2, b1, b2);

    // composite conv: x -> g_sp2 (replaces conv1+conv2)
    conv_gemm<2><<<dim3(12544 / 128, 192 / 64), 256>>>(nullptr, nullptr, x, nullptr, nullptr);

    // conv_p: (g_wav || g_sp2) -> d_out (bias + positions + transpose fused)
    conv_gemm<3><<<dim3((3136 + 127) / 128, 768 / 128), 256>>>(wp, bp, nullptr, pos, out);

    // cls row
    cls_kernel<<<192, 256>>>(cls, pos, out);
}

// round 3
// speedup vs baseline: 1.3728x; 1.2351x over previous
#include <cuda_runtime.h>

// ---------------- scratch (static device globals; no allocation) ----------------
__device__ float g_wav[64 * 768 * 196];      // 38.5 MB  [b][ch][14*14]
__device__ float g_sp2[64 * 192 * 196];      // 9.6 MB   [b][oc][14*14]
__device__ float g_wcomp[192 * 3 * 31 * 31]; // composed conv1∘conv2 weights
__device__ float g_bias[192 * 4];            // composed bias, 4 border cases

// ---------------- 4-level Haar == 16x16 2D Walsh-Hadamard per tile ----------------
__global__ void haar_kernel(const float* __restrict__ x) {
    int bid  = blockIdx.x;
    int tile = bid % 196;
    int bc   = bid / 196;
    int c    = bc % 3;
    int b    = bc / 3;
    int ti = tile / 14, tj = tile % 14;
    int t  = threadIdx.x;
    int dy = t >> 4, dx = t & 15;

    __shared__ float s[256];
    float v = x[((b * 3 + c) * 224 + ti * 16 + dy) * 224 + tj * 16 + dx];

#pragma unroll
    for (int st = 0; st < 8; ++st) {
        s[t] = v;
        __syncthreads();
        float u = s[t ^ (1 << st)];
        v = (t & (1 << st)) ? (u - v) : (v + u);
        __syncthreads();
    }

    int cm = t & 15, rm = t >> 4;
    int k1 = 2 * ((rm >> 0) & 1) + ((cm >> 0) & 1);
    int k2 = 2 * ((rm >> 1) & 1) + ((cm >> 1) & 1);
    int k3 = 2 * ((rm >> 2) & 1) + ((cm >> 2) & 1);
    int k4 = 2 * ((rm >> 3) & 1) + ((cm >> 3) & 1);
    int k  = ((k1 * 4 + k2) * 4 + k3) * 4 + k4;
    int ch = k * 3 + c;
    g_wav[(b * 768 + ch) * 196 + tile] = v * 0.0625f;
}

// ---------------- compose w_comp[o][c][dy][dx] = sum_m w2[o][m] ⊛ w1[m][c] -------
__global__ void compose_kernel(const float* __restrict__ w1,
                               const float* __restrict__ w2) {
    int o = blockIdx.x;
    __shared__ float s_w2[192 * 49];
    for (int i = threadIdx.x; i < 192 * 49; i += blockDim.x)
        s_w2[i] = w2[o * 192 * 49 + i];
    __syncthreads();

    for (int r = threadIdx.x; r < 2883; r += blockDim.x) {
        int c  = r / 961;
        int r2 = r - c * 961;
        int dy = r2 / 31, dx = r2 - (r2 / 31) * 31;
        float acc = 0.f;
#pragma unroll
        for (int ky2 = 0; ky2 < 7; ++ky2) {
            int ky1 = dy - 4 * ky2;
            if (ky1 < 0 || ky1 > 6) continue;
#pragma unroll
            for (int kx2 = 0; kx2 < 7; ++kx2) {
                int kx1 = dx - 4 * kx2;
                if (kx1 < 0 || kx1 > 6) continue;
                const float* w2p = &s_w2[ky2 * 7 + kx2];
                const float* w1p = &w1[(c * 7 + ky1) * 7 + kx1];
#pragma unroll 4
                for (int m = 0; m < 192; ++m)
                    acc += w2p[m * 49] * w1p[m * 147];
            }
        }
        g_wcomp[o * 2883 + r] = acc;
    }
}

// ---------------- composed bias: 4 border cases per output channel --------------
__global__ void bias_kernel(const float* __restrict__ w2,
                            const float* __restrict__ b1,
                            const float* __restrict__ b2) {
    int o = blockIdx.x;
    int m = threadIdx.x;
    float s00 = 0, s01 = 0, s10 = 0, s11 = 0;
    if (m < 192) {
        float bm = b1[m];
#pragma unroll
        for (int ky2 = 0; ky2 < 7; ++ky2)
#pragma unroll
            for (int kx2 = 0; kx2 < 7; ++kx2) {
                float w = w2[((o * 192 + m) * 7 + ky2) * 7 + kx2] * bm;
                s00 += w;
                if (kx2 >= 3) s01 += w;
                if (ky2 >= 3) s10 += w;
                if (ky2 >= 3 && kx2 >= 3) s11 += w;
            }
    }
    __shared__ float red[4][256];
    red[0][m] = s00; red[1][m] = s01; red[2][m] = s10; red[3][m] = s11;
    __syncthreads();
    for (int s = 128; s > 0; s >>= 1) {
        if (m < s) {
            red[0][m] += red[0][m + s];
            red[1][m] += red[1][m + s];
            red[2][m] += red[2][m + s];
            red[3][m] += red[3][m + s];
        }
        __syncthreads();
    }
    if (m == 0) {
        float bo = b2[o];
        g_bias[o * 4 + 0] = bo + red[0][0];
        g_bias[o * 4 + 1] = bo + red[1][0];
        g_bias[o * 4 + 2] = bo + red[2][0];
        g_bias[o * 4 + 3] = bo + red[3][0];
    }
}

// ---------------- bf16 split helpers ----------------
__device__ __forceinline__ unsigned f2bf(float f) {
    unsigned u = __float_as_uint(f);
    return (u + 0x7fffu + ((u >> 16) & 1u)) >> 16;   // round-to-nearest-even
}

#define MMA_BF16(c, a, b)                                                     \
    asm volatile(                                                             \
        "mma.sync.aligned.m16n8k16.row.col.f32.bf16.bf16.f32 "                \
        "{%0,%1,%2,%3},{%4,%5,%6,%7},{%8,%9},{%0,%1,%2,%3};"                  \
        : "+f"((c)[0]), "+f"((c)[1]), "+f"((c)[2]), "+f"((c)[3])              \
        : "r"((a)[0]), "r"((a)[1]), "r"((a)[2]), "r"((a)[3]),                 \
          "r"((b)[0]), "r"((b)[1]))

// ---------------- tensor-core implicit-GEMM convs (3-pass bf16 split) ------------
// MODE 2: composite conv  x * g_wcomp[192,3,31,31] s16 p15 -> g_sp2
//         M=192 N=12544 K=2883   BM=64  BN=128, warp 32x32
// MODE 3: conv_p (g_wav||g_sp2) * w[768,960,3,3] s2 p1 -> d_out
//         M=768 N=3136  K=8640   BM=128 BN=128, warp 64x32
template <int MODE>
__global__ void __launch_bounds__(256)
conv_mma(const float* __restrict__ A,
         const float* __restrict__ bias,
         const float* __restrict__ X,
         const float* __restrict__ positions,
         float* __restrict__ Cout)
{
    constexpr int BM = (MODE == 2) ? 64 : 128;
    constexpr int BN = 128;
    constexpr int K  = (MODE == 2) ? 2883 : 8640;
    constexpr int NT = (MODE == 2) ? 12544 : 3136;
    constexpr int P  = 12;                 // u32 pitch per row (8 data + 4 pad)
    constexpr int MF = (MODE == 2) ? 2 : 4;
    constexpr int NF = 4;

    __shared__ unsigned As_h[BM * P], As_l[BM * P];
    __shared__ unsigned Bs_h[BN * P], Bs_l[BN * P];

    const int tid = threadIdx.x;
    const int m0 = blockIdx.y * BM;
    const int n0 = blockIdx.x * BN;

    const int warp = tid >> 5, lane = tid & 31;
    const int grp = lane >> 2, tig = lane & 3;
    const int wm = (warp >> 2) * (MF * 16);
    const int wn = (warp & 3) * 32;

    const float* Aptr = (MODE == 2) ? (const float*)g_wcomp : A;

    // A staging mapping: thread -> (row am, AU u32 of consecutive k-pairs)
    const int am = (MODE == 2) ? (tid >> 2) : (tid >> 1);
    const int ak = (MODE == 2) ? ((tid & 3) * 4) : ((tid & 1) * 8);
    constexpr int AU = (MODE == 2) ? 2 : 4;

    // B staging mapping
    const int bn  = tid & 127;
    const int bkb = (tid >> 7) * 8;
    const int ng  = n0 + bn;
    const bool bvalid = (ng < NT);
    int b_, oy_, ox_;
    {
        int nn = bvalid ? ng : 0;
        if (MODE == 2) { b_ = nn / 196; int p = nn % 196; oy_ = p / 14; ox_ = p % 14; }
        else           { b_ = nn / 49;  int p = nn % 49;  oy_ = p / 7;  ox_ = p % 7;  }
    }

    float acc[MF][NF][4] = {};
    const float* Abase = Aptr + (m0 + am) * K;

    for (int k0 = 0; k0 < K; k0 += 16) {
        // ---- stage A (weights) as bf16 hi/lo ----
#pragma unroll
        for (int i = 0; i < AU; ++i) {
            int k = k0 + ak + 2 * i;
            float v0, v1;
            if (K % 16 == 0) { v0 = Abase[k]; v1 = Abase[k + 1]; }
            else {
                v0 = (k     < K) ? Abase[k]     : 0.f;
                v1 = (k + 1 < K) ? Abase[k + 1] : 0.f;
            }
            unsigned h0 = f2bf(v0), h1 = f2bf(v1);
            float l0 = v0 - __uint_as_float(h0 << 16);
            float l1 = v1 - __uint_as_float(h1 << 16);
            As_h[am * P + ak / 2 + i] = h0 | (h1 << 16);
            As_l[am * P + ak / 2 + i] = f2bf(l0) | (f2bf(l1) << 16);
        }
        // ---- stage B (im2col gather) as bf16 hi/lo ----
        float val[8];
#pragma unroll
        for (int i = 0; i < 8; ++i) {
            int k = k0 + bkb + i;
            float v = 0.f;
            if ((K % 16 == 0 || k < K) && bvalid) {
                if (MODE == 2) {
                    int c = k / 961; int r = k - c * 961;
                    int dy = r / 31; int dx = r - dy * 31;
                    int iy = oy_ * 16 + dy - 15, ix = ox_ * 16 + dx - 15;
                    if ((unsigned)iy < 224u && (unsigned)ix < 224u)
                        v = X[((b_ * 3 + c) * 224 + iy) * 224 + ix];
                } else {
                    int ch = k / 9; int r = k - ch * 9;
                    int ky = r / 3; int kx = r - ky * 3;
                    int iy = oy_ * 2 + ky - 1, ix = ox_ * 2 + kx - 1;
                    if ((unsigned)iy < 14u && (unsigned)ix < 14u)
                        v = (ch < 768)
                                ? g_wav[(b_ * 768 + ch) * 196 + iy * 14 + ix]
                                : g_sp2[(b_ * 192 + (ch - 768)) * 196 + iy * 14 + ix];
                }
            }
            val[i] = v;
        }
#pragma unroll
        for (int i = 0; i < 4; ++i) {
            unsigned h0 = f2bf(val[2 * i]), h1 = f2bf(val[2 * i + 1]);
            float l0 = val[2 * i]     - __uint_as_float(h0 << 16);
            float l1 = val[2 * i + 1] - __uint_as_float(h1 << 16);
            Bs_h[bn * P + bkb / 2 + i] = h0 | (h1 << 16);
            Bs_l[bn * P + bkb / 2 + i] = f2bf(l0) | (f2bf(l1) << 16);
        }
        __syncthreads();

        // ---- fragment loads (conflict-free: grp*12 + tig spans all 32 banks) ----
        unsigned ah[MF][4], al[MF][4], bh[NF][2], bl[NF][2];
#pragma unroll
        for (int mf = 0; mf < MF; ++mf) {
            int r0 = (wm + mf * 16 + grp) * P;
            int r1 = r0 + 8 * P;
            ah[mf][0] = As_h[r0 + tig];     ah[mf][1] = As_h[r1 + tig];
            ah[mf][2] = As_h[r0 + tig + 4]; ah[mf][3] = As_h[r1 + tig + 4];
            al[mf][0] = As_l[r0 + tig];     al[mf][1] = As_l[r1 + tig];
            al[mf][2] = As_l[r0 + tig + 4]; al[mf][3] = As_l[r1 + tig + 4];
        }
#pragma unroll
        for (int nf = 0; nf < NF; ++nf) {
            int rb = (wn + nf * 8 + grp) * P;
            bh[nf][0] = Bs_h[rb + tig]; bh[nf][1] = Bs_h[rb + tig + 4];
            bl[nf][0] = Bs_l[rb + tig]; bl[nf][1] = Bs_l[rb + tig + 4];
        }
        // ---- 3-pass split MMA: hi*hi + hi*lo + lo*hi ----
#pragma unroll
        for (int mf = 0; mf < MF; ++mf)
#pragma unroll
            for (int nf = 0; nf < NF; ++nf) {
                MMA_BF16(acc[mf][nf], ah[mf], bh[nf]);
                MMA_BF16(acc[mf][nf], ah[mf], bl[nf]);
                MMA_BF16(acc[mf][nf], al[mf], bh[nf]);
            }
        __syncthreads();
    }

    // ---- epilogue ----
#pragma unroll
    for (int mf = 0; mf < MF; ++mf) {
        int row0 = m0 + wm + mf * 16 + grp;
#pragma unroll
        for (int nf = 0; nf < NF; ++nf) {
            int col = n0 + wn + nf * 8 + 2 * tig;
#pragma unroll
            for (int e = 0; e < 4; ++e) {
                int oc = row0 + (e >> 1) * 8;
                int nn = col + (e & 1);
                float v = acc[mf][nf][e];
                if (MODE == 2) {
                    int b = nn / 196, p = nn % 196;
                    int oy = p / 14, ox = p % 14;
                    float bi = g_bias[oc * 4 + (oy == 0 ? 2 : 0) + (ox == 0 ? 1 : 0)];
                    g_sp2[(b * 192 + oc) * 196 + p] = v + bi;
                } else {
                    if (nn < NT) {
                        int b = nn / 49, p = nn % 49;
                        Cout[(b * 50 + 1 + p) * 768 + oc] =
                            v + bias[oc] + positions[(1 + p) * 768 + oc];
                    }
                }
            }
        }
    }
}

// ---------------- cls row ----------------
__global__ void cls_kernel(const float* __restrict__ cls,
                           const float* __restrict__ pos,
                           float* __restrict__ out) {
    int i = blockIdx.x * 256 + threadIdx.x;
    if (i < 64 * 768) {
        int b = i / 768, oc = i % 768;
        out[(b * 50) * 768 + oc] = cls[oc] + pos[oc];
    }
}

extern "C" void kernel_launch(void* const* d_in, const int* in_sizes, int n_in,
                              void* d_out, int out_size) {
    const float* x   = (const float*)d_in[0];
    const float* w1  = (const float*)d_in[1];
    const float* b1  = (const float*)d_in[2];
    const float* w2  = (const float*)d_in[3];
    const float* b2  = (const float*)d_in[4];
    const float* wp  = (const float*)d_in[5];
    const float* bp  = (const float*)d_in[6];
    const float* cls = (const float*)d_in[7];
    const float* pos = (const float*)d_in[8];
    float* out = (float*)d_out;

    haar_kernel<<<64 * 3 * 196, 256>>>(x);
    compose_kernel<<<192, 256>>>(w1, w2);
    bias_kernel<<<192, 256>>>(w2, b1, b2);

    // composite conv: x -> g_sp2
    conv_mma<2><<<dim3(12544 / 128, 192 / 64), 256>>>(nullptr, nullptr, x, nullptr, nullptr);

    // conv_p: (g_wav || g_sp2) -> d_out (bias + positions + transpose fused)
    conv_mma<3><<<dim3((3136 + 127) / 128, 768 / 128), 256>>>(wp, bp, nullptr, pos, out);

    cls_kernel<<<192, 256>>>(cls, pos, out);
}

// round 4
// speedup vs baseline: 4.0255x; 2.9325x over previous
#include <cuda_runtime.h>

// ---------------- scratch (static device globals; no allocation) ----------------
__device__ float g_wav[64 * 768 * 196];      // [b][ch][14*14]
__device__ float g_sp2[64 * 192 * 196];      // [b][oc][14*14]
__device__ float g_wcomp[192 * 3 * 31 * 31]; // composed conv1∘conv2 weights
__device__ float g_bias[192 * 4];            // composed bias, 4 border cases

// prepacked bf16 hi/lo operands (u32 = 2 bf16)
__device__ unsigned g_A2h[192 * 1448],  g_A2l[192 * 1448];   // wcomp  [192][Kp=2896]
__device__ unsigned g_A3h[768 * 4320],  g_A3l[768 * 4320];   // wp     [768][8640]
__device__ unsigned g_B2h[12544 * 1448], g_B2l[12544 * 1448];// im2col composite
__device__ unsigned g_B3h[3200 * 4320],  g_B3l[3200 * 4320]; // im2col conv_p (N padded)

// ---------------- bf16 split helpers ----------------
__device__ __forceinline__ unsigned f2bf(float f) {
    unsigned u = __float_as_uint(f);
    return (u + 0x7fffu + ((u >> 16) & 1u)) >> 16;
}
__device__ __forceinline__ void split2(float v0, float v1, unsigned& hi, unsigned& lo) {
    unsigned h0 = f2bf(v0), h1 = f2bf(v1);
    float l0 = v0 - __uint_as_float(h0 << 16);
    float l1 = v1 - __uint_as_float(h1 << 16);
    hi = h0 | (h1 << 16);
    lo = f2bf(l0) | (f2bf(l1) << 16);
}

// ---------------- 4-level Haar == 16x16 2D Walsh-Hadamard per tile ----------------
__global__ void haar_kernel(const float* __restrict__ x) {
    int bid  = blockIdx.x;
    int tile = bid % 196;
    int bc   = bid / 196;
    int c    = bc % 3;
    int b    = bc / 3;
    int ti = tile / 14, tj = tile % 14;
    int t  = threadIdx.x;
    int dy = t >> 4, dx = t & 15;

    __shared__ float s[256];
    float v = x[((b * 3 + c) * 224 + ti * 16 + dy) * 224 + tj * 16 + dx];

#pragma unroll
    for (int st = 0; st < 8; ++st) {
        s[t] = v;
        __syncthreads();
        float u = s[t ^ (1 << st)];
        v = (t & (1 << st)) ? (u - v) : (v + u);
        __syncthreads();
    }

    int cm = t & 15, rm = t >> 4;
    int k1 = 2 * ((rm >> 0) & 1) + ((cm >> 0) & 1);
    int k2 = 2 * ((rm >> 1) & 1) + ((cm >> 1) & 1);
    int k3 = 2 * ((rm >> 2) & 1) + ((cm >> 2) & 1);
    int k4 = 2 * ((rm >> 3) & 1) + ((cm >> 3) & 1);
    int k  = ((k1 * 4 + k2) * 4 + k3) * 4 + k4;
    g_wav[(b * 768 + (k * 3 + c)) * 196 + tile] = v * 0.0625f;
}

// ---------------- compose: fully smem-resident ----------------
__global__ void __launch_bounds__(256) compose_kernel(const float* __restrict__ w1,
                                                      const float* __restrict__ w2) {
    int o = blockIdx.x / 3, c = blockIdx.x % 3;
    __shared__ float s_w1[192 * 49];   // w1[:, c, :, :]
    __shared__ float s_w2[32 * 49];    // w2[o, chunk, :, :]

    for (int i = threadIdx.x; i < 192 * 49; i += 256) {
        int m = i / 49, r = i - m * 49;
        s_w1[i] = w1[m * 147 + c * 49 + r];
    }

    // per-thread outputs idx = tid + u*256  (961 outputs)
    float acc[4] = {0.f, 0.f, 0.f, 0.f};
    bool  uval[4];
    int   oAA2[4], oAA1[4], oAB2[4], oAB1[4], oBA2[4], oBA1[4], oBB2[4], oBB1[4];
    bool  vx[4], vy[4];
#pragma unroll
    for (int u = 0; u < 4; ++u) {
        int idx = threadIdx.x + u * 256;
        uval[u] = (idx < 961);
        int ii = uval[u] ? idx : 0;
        int dy = ii / 31, dx = ii - (ii / 31) * 31;
        int kyA = min(dy >> 2, 6); int ky1A = dy - 4 * kyA;
        vy[u] = (kyA >= 1) && (ky1A + 4 <= 6);
        int kyB = kyA - 1, ky1B = ky1A + 4;
        int kxA = min(dx >> 2, 6); int kx1A = dx - 4 * kxA;
        vx[u] = (kxA >= 1) && (kx1A + 4 <= 6);
        int kxB = kxA - 1, kx1B = kx1A + 4;
        oAA2[u] = kyA * 7 + kxA; oAA1[u] = ky1A * 7 + kx1A;
        oAB2[u] = kyA * 7 + kxB; oAB1[u] = ky1A * 7 + kx1B;
        oBA2[u] = kyB * 7 + kxA; oBA1[u] = ky1B * 7 + kx1A;
        oBB2[u] = kyB * 7 + kxB; oBB1[u] = ky1B * 7 + kx1B;
    }

    for (int mc = 0; mc < 192; mc += 32) {
        __syncthreads();
        for (int i = threadIdx.x; i < 32 * 49; i += 256)
            s_w2[i] = w2[o * 9408 + mc * 49 + i];
        __syncthreads();
#pragma unroll 4
        for (int m = 0; m < 32; ++m) {
            const float* w2m = &s_w2[m * 49];
            const float* w1m = &s_w1[(mc + m) * 49];
#pragma unroll
            for (int u = 0; u < 4; ++u) {
                if (!uval[u]) continue;
                acc[u] += w2m[oAA2[u]] * w1m[oAA1[u]];
                if (vx[u]) acc[u] += w2m[oAB2[u]] * w1m[oAB1[u]];
                if (vy[u]) acc[u] += w2m[oBA2[u]] * w1m[oBA1[u]];
                if (vy[u] && vx[u]) acc[u] += w2m[oBB2[u]] * w1m[oBB1[u]];
            }
        }
    }
#pragma unroll
    for (int u = 0; u < 4; ++u) {
        int idx = threadIdx.x + u * 256;
        if (idx < 961) g_wcomp[o * 2883 + c * 961 + idx] = acc[u];
    }
}

// ---------------- composed bias: 4 border cases ----------------
__global__ void bias_kernel(const float* __restrict__ w2,
                            const float* __restrict__ b1,
                            const float* __restrict__ b2) {
    int o = blockIdx.x;
    int m = threadIdx.x;
    float s00 = 0, s01 = 0, s10 = 0, s11 = 0;
    if (m < 192) {
        float bm = b1[m];
#pragma unroll
        for (int ky2 = 0; ky2 < 7; ++ky2)
#pragma unroll
            for (int kx2 = 0; kx2 < 7; ++kx2) {
                float w = w2[((o * 192 + m) * 7 + ky2) * 7 + kx2] * bm;
                s00 += w;
                if (kx2 >= 3) s01 += w;
                if (ky2 >= 3) s10 += w;
                if (ky2 >= 3 && kx2 >= 3) s11 += w;
            }
    }
    __shared__ float red[4][256];
    red[0][m] = s00; red[1][m] = s01; red[2][m] = s10; red[3][m] = s11;
    __syncthreads();
    for (int s = 128; s > 0; s >>= 1) {
        if (m < s) {
            red[0][m] += red[0][m + s];
            red[1][m] += red[1][m + s];
            red[2][m] += red[2][m + s];
            red[3][m] += red[3][m + s];
        }
        __syncthreads();
    }
    if (m == 0) {
        float bo = b2[o];
        g_bias[o * 4 + 0] = bo + red[0][0];
        g_bias[o * 4 + 1] = bo + red[1][0];
        g_bias[o * 4 + 2] = bo + red[2][0];
        g_bias[o * 4 + 3] = bo + red[3][0];
    }
}

// ---------------- pack A (weights) ----------------
__global__ void pack_a2() {                      // g_wcomp [192][2883] -> Kp 2896
    int t = blockIdx.x * 256 + threadIdx.x;      // 192*1448
    int m = t / 1448, j = t - (t / 1448) * 1448;
    int k = 2 * j;
    float v0 = (k     < 2883) ? g_wcomp[m * 2883 + k]     : 0.f;
    float v1 = (k + 1 < 2883) ? g_wcomp[m * 2883 + k + 1] : 0.f;
    split2(v0, v1, g_A2h[t], g_A2l[t]);
}
__global__ void pack_a3(const float* __restrict__ wp) {   // [768][8640]
    int t = blockIdx.x * 256 + threadIdx.x;               // 768*4320
    float v0 = wp[2 * t], v1 = wp[2 * t + 1];
    split2(v0, v1, g_A3h[t], g_A3l[t]);
}

// ---------------- pack B2 (im2col composite conv from x) ----------------
__global__ void pack_b2(const float* __restrict__ x) {
    int t = blockIdx.x * 256 + threadIdx.x;      // 12544*1448
    int n = t / 1448, j = t - (t / 1448) * 1448;
    int b = n / 196, p = n - (n / 196) * 196;
    int oy = p / 14, ox = p - (p / 14) * 14;
    float v[2];
#pragma unroll
    for (int e = 0; e < 2; ++e) {
        int k = 2 * j + e;
        float vv = 0.f;
        if (k < 2883) {
            int c = k / 961, r = k - c * 961;
            int dy = r / 31, dx = r - (r / 31) * 31;
            int iy = oy * 16 + dy - 15, ix = ox * 16 + dx - 15;
            if ((unsigned)iy < 224u && (unsigned)ix < 224u)
                vv = x[((b * 3 + c) * 224 + iy) * 224 + ix];
        }
        v[e] = vv;
    }
    split2(v[0], v[1], g_B2h[t], g_B2l[t]);
}

// ---------------- pack B3 (im2col conv_p from wav||sp2) ----------------
__global__ void pack_b3() {
    int t = blockIdx.x * 256 + threadIdx.x;      // 3200*4320
    int n = t / 4320, j = t - (t / 4320) * 4320;
    float v[2];
    if (n < 3136) {
        int b = n / 49, p = n - (n / 49) * 49;
        int oy = p / 7, ox = p - (p / 7) * 7;
#pragma unroll
        for (int e = 0; e < 2; ++e) {
            int k = 2 * j + e;
            int ch = k / 9, r = k - ch * 9;
            int ky = r / 3, kx = r - (r / 3) * 3;
            int iy = oy * 2 + ky - 1, ix = ox * 2 + kx - 1;
            float vv = 0.f;
            if ((unsigned)iy < 14u && (unsigned)ix < 14u)
                vv = (ch < 768) ? g_wav[(b * 768 + ch) * 196 + iy * 14 + ix]
                                : g_sp2[(b * 192 + (ch - 768)) * 196 + iy * 14 + ix];
            v[e] = vv;
        }
    } else { v[0] = v[1] = 0.f; }
    split2(v[0], v[1], g_B3h[t], g_B3l[t]);
}

// ---------------- MMA ----------------
#define MMA_BF16(c, a, b)                                                     \
    asm volatile(                                                             \
        "mma.sync.aligned.m16n8k16.row.col.f32.bf16.bf16.f32 "                \
        "{%0,%1,%2,%3},{%4,%5,%6,%7},{%8,%9},{%0,%1,%2,%3};"                  \
        : "+f"((c)[0]), "+f"((c)[1]), "+f"((c)[2]), "+f"((c)[3])              \
        : "r"((a)[0]), "r"((a)[1]), "r"((a)[2]), "r"((a)[3]),                 \
          "r"((b)[0]), "r"((b)[1]))

__device__ __forceinline__ void cp16(unsigned* s, const unsigned* g) {
    unsigned sa = (unsigned)__cvta_generic_to_shared(s);
    asm volatile("cp.async.cg.shared.global [%0], [%1], 16;" :: "r"(sa), "l"(g));
}

// ---------------- pure bf16 GEMM, 3-pass split, cp.async double-buffered ----------
// MODE 2: M=192 (BM=64,grid.y=3)  N=12544 Kp=2896 -> g_sp2 (+border bias)
// MODE 3: M=768 (BM=128,grid.y=6) N=3200(3136) Kp=8640 -> d_out (+bias+pos+transpose)
template <int MODE>
__global__ void __launch_bounds__(256)
gemm_bf16(const float* __restrict__ bias,
          const float* __restrict__ positions,
          float* __restrict__ Cout)
{
    constexpr int BM = (MODE == 2) ? 64 : 128;
    constexpr int MF = (MODE == 2) ? 2 : 4;
    constexpr int NF = 4;
    constexpr int KP = (MODE == 2) ? 2896 : 8640;
    constexpr int KU = KP / 2;
    constexpr int NT = (MODE == 2) ? 12544 : 3136;
    constexpr int P  = 12;
    constexpr int NIT = KP / 16;

    __shared__ unsigned As_h[2][BM * P], As_l[2][BM * P];
    __shared__ unsigned Bs_h[2][128 * P], Bs_l[2][128 * P];

    const unsigned* Agh = (MODE == 2) ? g_A2h : g_A3h;
    const unsigned* Agl = (MODE == 2) ? g_A2l : g_A3l;
    const unsigned* Bgh = (MODE == 2) ? g_B2h : g_B3h;
    const unsigned* Bgl = (MODE == 2) ? g_B2l : g_B3l;

    const int tid = threadIdx.x;
    const int m0 = blockIdx.y * BM, n0 = blockIdx.x * 128;
    const int warp = tid >> 5, lane = tid & 31, grp = lane >> 2, tig = lane & 3;
    const int wm = (warp >> 2) * (MF * 16), wn = (warp & 3) * 32;

    const int arow = tid >> 1, aq = (tid & 1) * 4;

    float acc[MF][NF][4] = {};

#define STAGE(buf, it) do {                                                    \
        int ku0 = (it) * 8;                                                    \
        if (MODE != 2 || tid < 128) {                                          \
            cp16(&As_h[buf][arow * P + aq], Agh + (m0 + arow) * KU + ku0 + aq);\
            cp16(&As_l[buf][arow * P + aq], Agl + (m0 + arow) * KU + ku0 + aq);\
        }                                                                      \
        cp16(&Bs_h[buf][arow * P + aq], Bgh + (n0 + arow) * KU + ku0 + aq);    \
        cp16(&Bs_l[buf][arow * P + aq], Bgl + (n0 + arow) * KU + ku0 + aq);    \
        asm volatile("cp.async.commit_group;");                                \
    } while (0)

    STAGE(0, 0);
    int buf = 0;

    for (int it = 0; it < NIT; ++it) {
        asm volatile("cp.async.wait_group 0;");
        __syncthreads();
        if (it + 1 < NIT) STAGE(buf ^ 1, it + 1);

        unsigned ah[MF][4], al[MF][4], bh[NF][2], bl[NF][2];
#pragma unroll
        for (int mf = 0; mf < MF; ++mf) {
            int r0 = (wm + mf * 16 + grp) * P, r1 = r0 + 8 * P;
            ah[mf][0] = As_h[buf][r0 + tig];     ah[mf][1] = As_h[buf][r1 + tig];
            ah[mf][2] = As_h[buf][r0 + tig + 4]; ah[mf][3] = As_h[buf][r1 + tig + 4];
            al[mf][0] = As_l[buf][r0 + tig];     al[mf][1] = As_l[buf][r1 + tig];
            al[mf][2] = As_l[buf][r0 + tig + 4]; al[mf][3] = As_l[buf][r1 + tig + 4];
        }
#pragma unroll
        for (int nf = 0; nf < NF; ++nf) {
            int rb = (wn + nf * 8 + grp) * P;
            bh[nf][0] = Bs_h[buf][rb + tig]; bh[nf][1] = Bs_h[buf][rb + tig + 4];
            bl[nf][0] = Bs_l[buf][rb + tig]; bl[nf][1] = Bs_l[buf][rb + tig + 4];
        }
#pragma unroll
        for (int mf = 0; mf < MF; ++mf)
#pragma unroll
            for (int nf = 0; nf < NF; ++nf) {
                MMA_BF16(acc[mf][nf], ah[mf], bh[nf]);
                MMA_BF16(acc[mf][nf], ah[mf], bl[nf]);
                MMA_BF16(acc[mf][nf], al[mf], bh[nf]);
            }
        buf ^= 1;
    }
#undef STAGE

    // ---- epilogue ----
#pragma unroll
    for (int mf = 0; mf < MF; ++mf) {
        int row0 = m0 + wm + mf * 16 + grp;
#pragma unroll
        for (int nf = 0; nf < NF; ++nf) {
            int col = n0 + wn + nf * 8 + 2 * tig;
#pragma unroll
            for (int e = 0; e < 4; ++e) {
                int oc = row0 + (e >> 1) * 8;
                int nn = col + (e & 1);
                float v = acc[mf][nf][e];
                if (MODE == 2) {
                    int b = nn / 196, p = nn - (nn / 196) * 196;
                    int oy = p / 14, ox = p - (p / 14) * 14;
                    float bi = g_bias[oc * 4 + (oy == 0 ? 2 : 0) + (ox == 0 ? 1 : 0)];
                    g_sp2[(b * 192 + oc) * 196 + p] = v + bi;
                } else {
                    if (nn < NT) {
                        int b = nn / 49, p = nn - (nn / 49) * 49;
                        Cout[(b * 50 + 1 + p) * 768 + oc] =
                            v + bias[oc] + positions[(1 + p) * 768 + oc];
                    }
                }
            }
        }
    }
}

// ---------------- cls row ----------------
__global__ void cls_kernel(const float* __restrict__ cls,
                           const float* __restrict__ pos,
                           float* __restrict__ out) {
    int i = blockIdx.x * 256 + threadIdx.x;
    if (i < 64 * 768) {
        int b = i / 768, oc = i % 768;
        out[(b * 50) * 768 + oc] = cls[oc] + pos[oc];
    }
}

extern "C" void kernel_launch(void* const* d_in, const int* in_sizes, int n_in,
                              void* d_out, int out_size) {
    const float* x   = (const float*)d_in[0];
    const float* w1  = (const float*)d_in[1];
    const float* b1  = (const float*)d_in[2];
    const float* w2  = (const float*)d_in[3];
    const float* b2  = (const float*)d_in[4];
    const float* wp  = (const float*)d_in[5];
    const float* bp  = (const float*)d_in[6];
    const float* cls = (const float*)d_in[7];
    const float* pos = (const float*)d_in[8];
    float* out = (float*)d_out;

    haar_kernel<<<64 * 3 * 196, 256>>>(x);
    compose_kernel<<<576, 256>>>(w1, w2);
    bias_kernel<<<192, 256>>>(w2, b1, b2);

    pack_a2<<<192 * 1448 / 256, 256>>>();
    pack_a3<<<768 * 4320 / 256, 256>>>(wp);
    pack_b2<<<12544 * 1448 / 256, 256>>>(x);

    gemm_bf16<2><<<dim3(12544 / 128, 3), 256>>>(nullptr, nullptr, nullptr);

    pack_b3<<<3200 * 4320 / 256, 256>>>();

    gemm_bf16<3><<<dim3(3200 / 128, 6), 256>>>(bp, pos, out);

    cls_kernel<<<192, 256>>>(cls, pos, out);
}